// round 14
// baseline (speedup 1.0000x reference)
#include <cuda_runtime.h>
#include <cstdint>

// Hyperelasticity: closed-form Neo-Hookean stress.
// PK1 = MU*F + (LAM*lnJ - MU)*F^{-T};  PK2 = sym(F^{-1} PK1);  sig = sym(PK1 F^T)/J
//
// R11 structure (warp-autonomous, 96 pts/warp, triple-buffered cp.async
// input, rotating output staging). Output flushed with WRITE-THROUGH
// STG.128 (__stwt) so the 108 MB store stream does not allocate/churn L2;
// input prefetches carry L2::evict_last so the 36 MB input stays resident
// across graph replays -> steady-state DRAM drops ~144 MB -> ~108 MB.
// (Resubmission of R13: previous round was an infra failure, no data.)
#define MU  1.0f
#define LAM 1.0f
#define BS  128
#define WPB (BS / 32)

__device__ __forceinline__ uint32_t smem_u32(const void* p) {
    return (uint32_t)__cvta_generic_to_shared(p);
}
__device__ __forceinline__ uint64_t evict_last_policy() {
    uint64_t p;
    asm volatile("createpolicy.fractional.L2::evict_last.b64 %0, 1.0;\n" : "=l"(p));
    return p;
}
__device__ __forceinline__ void cp_async16_el(uint32_t dst, const void* src, uint64_t pol) {
    asm volatile("cp.async.cg.shared.global.L2::cache_hint [%0], [%1], 16, %2;\n"
                 :: "r"(dst), "l"(src), "l"(pol));
}
__device__ __forceinline__ void cp_commit() { asm volatile("cp.async.commit_group;\n"); }
__device__ __forceinline__ void cp_wait2()  { asm volatile("cp.async.wait_group 2;\n" ::: "memory"); }
__device__ __forceinline__ void cp_wait1()  { asm volatile("cp.async.wait_group 1;\n" ::: "memory"); }
__device__ __forceinline__ void cp_wait0()  { asm volatile("cp.async.wait_group 0;\n" ::: "memory"); }

__device__ __forceinline__ void compute_point(const float* __restrict__ Fp,
                                              float* __restrict__ o1,
                                              float* __restrict__ o2,
                                              float* __restrict__ o3)
{
    float a = Fp[0], b = Fp[1], c = Fp[2];
    float d = Fp[3], e = Fp[4], f = Fp[5];
    float g = Fp[6], h = Fp[7], i = Fp[8];

    // cofactors: F^{-T} = C/J, F^{-1} = C^T/J
    float C00 = fmaf(e, i, -f * h);
    float C01 = fmaf(f, g, -d * i);
    float C02 = fmaf(d, h, -e * g);
    float C10 = fmaf(c, h, -b * i);
    float C11 = fmaf(a, i, -c * g);
    float C12 = fmaf(b, g, -a * h);
    float C20 = fmaf(b, f, -c * e);
    float C21 = fmaf(c, d, -a * f);
    float C22 = fmaf(a, e, -b * d);

    float J   = a * C00 + b * C01 + c * C02;
    float rJ  = __frcp_rn(J);
    float lnJ = __logf(J);

    float s = (LAM * lnJ - MU) * rJ;
    float P00 = fmaf(s, C00, MU * a);
    float P01 = fmaf(s, C01, MU * b);
    float P02 = fmaf(s, C02, MU * c);
    float P10 = fmaf(s, C10, MU * d);
    float P11 = fmaf(s, C11, MU * e);
    float P12 = fmaf(s, C12, MU * f);
    float P20 = fmaf(s, C20, MU * g);
    float P21 = fmaf(s, C21, MU * h);
    float P22 = fmaf(s, C22, MU * i);

    // Finv = C^T/J
    float I00 = C00 * rJ, I01 = C10 * rJ, I02 = C20 * rJ;
    float I10 = C01 * rJ, I11 = C11 * rJ, I12 = C21 * rJ;
    float I20 = C02 * rJ, I21 = C12 * rJ, I22 = C22 * rJ;

    float M00 = I00*P00 + I01*P10 + I02*P20;
    float M01 = I00*P01 + I01*P11 + I02*P21;
    float M02 = I00*P02 + I01*P12 + I02*P22;
    float M10 = I10*P00 + I11*P10 + I12*P20;
    float M11 = I10*P01 + I11*P11 + I12*P21;
    float M12 = I10*P02 + I11*P12 + I12*P22;
    float M20 = I20*P00 + I21*P10 + I22*P20;
    float M21 = I20*P01 + I21*P11 + I22*P21;
    float M22 = I20*P02 + I21*P12 + I22*P22;

    float S01 = 0.5f * (M01 + M10);
    float S02 = 0.5f * (M02 + M20);
    float S12 = 0.5f * (M12 + M21);

    float T00 = P00*a + P01*b + P02*c;
    float T01 = P00*d + P01*e + P02*f;
    float T02 = P00*g + P01*h + P02*i;
    float T10 = P10*a + P11*b + P12*c;
    float T11 = P10*d + P11*e + P12*f;
    float T12 = P10*g + P11*h + P12*i;
    float T20 = P20*a + P21*b + P22*c;
    float T21 = P20*d + P21*e + P22*f;
    float T22 = P20*g + P21*h + P22*i;

    o1[0] = P00; o1[1] = P01; o1[2] = P02;
    o1[3] = P10; o1[4] = P11; o1[5] = P12;
    o1[6] = P20; o1[7] = P21; o1[8] = P22;

    o2[0] = M00; o2[1] = S01; o2[2] = S02;
    o2[3] = S01; o2[4] = M11; o2[5] = S12;
    o2[6] = S02; o2[7] = S12; o2[8] = M22;

    float G01 = 0.5f * (T01 + T10) * rJ;
    float G02 = 0.5f * (T02 + T20) * rJ;
    float G12 = 0.5f * (T12 + T21) * rJ;
    o3[0] = T00 * rJ; o3[1] = G01;      o3[2] = G02;
    o3[3] = G01;      o3[4] = T11 * rJ; o3[5] = G12;
    o3[6] = G02;      o3[7] = G12;      o3[8] = T22 * rJ;
}

// flush a staged 288-float region buffer to gmem with write-through stores
__device__ __forceinline__ void flush_buf(const float* __restrict__ sBuf,
                                          float* __restrict__ dst_f, int lane)
{
    float4* dst = (float4*)dst_f;
    const float4* q = (const float4*)sBuf;
    __stwt(dst + lane,      q[lane]);
    __stwt(dst + lane + 32, q[lane + 32]);
    if (lane < 8) __stwt(dst + lane + 64, q[lane + 64]);
}

__device__ __forceinline__ void stage_buf(float* __restrict__ sBuf,
                                          const float* __restrict__ o, int lane)
{
    #pragma unroll
    for (int k = 0; k < 9; k++) sBuf[lane * 9 + k] = o[k];
}

__device__ __forceinline__ void do_subtile(const float* __restrict__ sIn,
                                           float* __restrict__ b0,
                                           float* __restrict__ b1,
                                           float* __restrict__ out,
                                           size_t nn, long base, int lane)
{
    float Fp[9], o1[9], o2[9], o3[9];
    #pragma unroll
    for (int k = 0; k < 9; k++) Fp[k] = sIn[lane * 9 + k];

    compute_point(Fp, o1, o2, o3);

    stage_buf(b0, o1, lane);
    __syncwarp();
    flush_buf(b0, out + (size_t)base * 9, lane);

    stage_buf(b1, o2, lane);
    __syncwarp();
    flush_buf(b1, out + nn + (size_t)base * 9, lane);

    stage_buf(b0, o3, lane);
    __syncwarp();
    flush_buf(b0, out + 2 * nn + (size_t)base * 9, lane);
}

__device__ __forceinline__ void prefetch_subtile(uint32_t dstBase,
                                                 const float4* __restrict__ src,
                                                 int lane, uint64_t pol)
{
    cp_async16_el(dstBase + lane * 16,        src + lane,      pol);
    cp_async16_el(dstBase + (lane + 32) * 16, src + lane + 32, pol);
    if (lane < 8) cp_async16_el(dstBase + (lane + 64) * 16, src + lane + 64, pol);
    cp_commit();
}

__global__ __launch_bounds__(BS, 9)
void hyper_kernel(const float* __restrict__ Fin,
                  float* __restrict__ out,
                  int n)
{
    __shared__ __align__(16) float sIn[WPB][3][288];   // triple-buffered input
    __shared__ __align__(16) float sOut[WPB][2][288];  // rotating output buffers

    const int warp = threadIdx.x >> 5;
    const int lane = threadIdx.x & 31;
    const long base0 = (long)blockIdx.x * (BS * 3) + warp * 96;  // 96 pts/warp
    const size_t nn = (size_t)n * 9;

    float* b0 = sOut[warp][0];
    float* b1 = sOut[warp][1];

    if (base0 + 96 <= n) {
        const uint64_t pol = evict_last_policy();

        prefetch_subtile(smem_u32(sIn[warp][0]),
                         (const float4*)(Fin + (size_t)base0 * 9), lane, pol);
        prefetch_subtile(smem_u32(sIn[warp][1]),
                         (const float4*)(Fin + (size_t)(base0 + 32) * 9), lane, pol);
        prefetch_subtile(smem_u32(sIn[warp][2]),
                         (const float4*)(Fin + (size_t)(base0 + 64) * 9), lane, pol);

        cp_wait2();
        __syncwarp();
        do_subtile(sIn[warp][0], b0, b1, out, nn, base0, lane);

        cp_wait1();
        __syncwarp();
        do_subtile(sIn[warp][1], b0, b1, out, nn, base0 + 32, lane);

        cp_wait0();
        __syncwarp();
        do_subtile(sIn[warp][2], b0, b1, out, nn, base0 + 64, lane);
    } else {
        // ---- tail: scalar guarded path ----
        #pragma unroll
        for (int s = 0; s < 3; s++) {
            long idx = base0 + s * 32 + lane;
            if (idx < n) {
                float Fp[9], o1[9], o2[9], o3[9];
                #pragma unroll
                for (int k = 0; k < 9; k++) Fp[k] = Fin[(size_t)idx * 9 + k];
                compute_point(Fp, o1, o2, o3);
                #pragma unroll
                for (int k = 0; k < 9; k++) {
                    out[(size_t)idx * 9 + k]          = o1[k];
                    out[nn + (size_t)idx * 9 + k]     = o2[k];
                    out[2 * nn + (size_t)idx * 9 + k] = o3[k];
                }
            }
        }
    }
}

extern "C" void kernel_launch(void* const* d_in, const int* in_sizes, int n_in,
                              void* d_out, int out_size)
{
    const float* F = (const float*)d_in[0];
    float* out = (float*)d_out;
    int n = in_sizes[0] / 9;

    int pts_per_block = BS * 3;   // 96 per warp, 4 warps
    int blocks = (n + pts_per_block - 1) / pts_per_block;
    hyper_kernel<<<blocks, BS>>>(F, out, n);
}

// round 15
// speedup vs baseline: 1.1979x; 1.1979x over previous
#include <cuda_runtime.h>
#include <cstdint>

// Hyperelasticity: closed-form Neo-Hookean stress.
// PK1 = MU*F + (LAM*lnJ - MU)*F^{-T};  PK2 = sym(F^{-1} PK1);  sig = sym(PK1 F^T)/J
//
// FINAL (= R11, the session best at 24.6us): warp-autonomous, 96 points/warp
// in three sub-tiles, triple-buffered cp.async input prefetch (6.75
// cp.async/lane in flight), output staged through two rotating per-warp smem
// buffers, flushed with coalesced streaming STG.128 (__stcs). No block
// barriers. Condemned with evidence: TMA bulk stores (R9/R10: +4-6us wall
// drain cost), evict_last input policy (R12: neutral), write-through stores
// (R14: +4.8us wall). Steady-state limiter: mixed R/W HBM bandwidth.
#define MU  1.0f
#define LAM 1.0f
#define BS  128
#define WPB (BS / 32)

__device__ __forceinline__ uint32_t smem_u32(const void* p) {
    return (uint32_t)__cvta_generic_to_shared(p);
}
__device__ __forceinline__ void cp_async16(uint32_t dst, const void* src) {
    asm volatile("cp.async.cg.shared.global [%0], [%1], 16;\n" :: "r"(dst), "l"(src));
}
__device__ __forceinline__ void cp_commit() { asm volatile("cp.async.commit_group;\n"); }
__device__ __forceinline__ void cp_wait2()  { asm volatile("cp.async.wait_group 2;\n" ::: "memory"); }
__device__ __forceinline__ void cp_wait1()  { asm volatile("cp.async.wait_group 1;\n" ::: "memory"); }
__device__ __forceinline__ void cp_wait0()  { asm volatile("cp.async.wait_group 0;\n" ::: "memory"); }

__device__ __forceinline__ void compute_point(const float* __restrict__ Fp,
                                              float* __restrict__ o1,
                                              float* __restrict__ o2,
                                              float* __restrict__ o3)
{
    float a = Fp[0], b = Fp[1], c = Fp[2];
    float d = Fp[3], e = Fp[4], f = Fp[5];
    float g = Fp[6], h = Fp[7], i = Fp[8];

    // cofactors: F^{-T} = C/J, F^{-1} = C^T/J
    float C00 = fmaf(e, i, -f * h);
    float C01 = fmaf(f, g, -d * i);
    float C02 = fmaf(d, h, -e * g);
    float C10 = fmaf(c, h, -b * i);
    float C11 = fmaf(a, i, -c * g);
    float C12 = fmaf(b, g, -a * h);
    float C20 = fmaf(b, f, -c * e);
    float C21 = fmaf(c, d, -a * f);
    float C22 = fmaf(a, e, -b * d);

    float J   = a * C00 + b * C01 + c * C02;
    float rJ  = __frcp_rn(J);
    float lnJ = __logf(J);

    float s = (LAM * lnJ - MU) * rJ;
    float P00 = fmaf(s, C00, MU * a);
    float P01 = fmaf(s, C01, MU * b);
    float P02 = fmaf(s, C02, MU * c);
    float P10 = fmaf(s, C10, MU * d);
    float P11 = fmaf(s, C11, MU * e);
    float P12 = fmaf(s, C12, MU * f);
    float P20 = fmaf(s, C20, MU * g);
    float P21 = fmaf(s, C21, MU * h);
    float P22 = fmaf(s, C22, MU * i);

    // Finv = C^T/J
    float I00 = C00 * rJ, I01 = C10 * rJ, I02 = C20 * rJ;
    float I10 = C01 * rJ, I11 = C11 * rJ, I12 = C21 * rJ;
    float I20 = C02 * rJ, I21 = C12 * rJ, I22 = C22 * rJ;

    float M00 = I00*P00 + I01*P10 + I02*P20;
    float M01 = I00*P01 + I01*P11 + I02*P21;
    float M02 = I00*P02 + I01*P12 + I02*P22;
    float M10 = I10*P00 + I11*P10 + I12*P20;
    float M11 = I10*P01 + I11*P11 + I12*P21;
    float M12 = I10*P02 + I11*P12 + I12*P22;
    float M20 = I20*P00 + I21*P10 + I22*P20;
    float M21 = I20*P01 + I21*P11 + I22*P21;
    float M22 = I20*P02 + I21*P12 + I22*P22;

    float S01 = 0.5f * (M01 + M10);
    float S02 = 0.5f * (M02 + M20);
    float S12 = 0.5f * (M12 + M21);

    float T00 = P00*a + P01*b + P02*c;
    float T01 = P00*d + P01*e + P02*f;
    float T02 = P00*g + P01*h + P02*i;
    float T10 = P10*a + P11*b + P12*c;
    float T11 = P10*d + P11*e + P12*f;
    float T12 = P10*g + P11*h + P12*i;
    float T20 = P20*a + P21*b + P22*c;
    float T21 = P20*d + P21*e + P22*f;
    float T22 = P20*g + P21*h + P22*i;

    o1[0] = P00; o1[1] = P01; o1[2] = P02;
    o1[3] = P10; o1[4] = P11; o1[5] = P12;
    o1[6] = P20; o1[7] = P21; o1[8] = P22;

    o2[0] = M00; o2[1] = S01; o2[2] = S02;
    o2[3] = S01; o2[4] = M11; o2[5] = S12;
    o2[6] = S02; o2[7] = S12; o2[8] = M22;

    float G01 = 0.5f * (T01 + T10) * rJ;
    float G02 = 0.5f * (T02 + T20) * rJ;
    float G12 = 0.5f * (T12 + T21) * rJ;
    o3[0] = T00 * rJ; o3[1] = G01;      o3[2] = G02;
    o3[3] = G01;      o3[4] = T11 * rJ; o3[5] = G12;
    o3[6] = G02;      o3[7] = G12;      o3[8] = T22 * rJ;
}

// flush a staged 288-float region buffer to gmem, coalesced streaming stores
__device__ __forceinline__ void flush_buf(const float* __restrict__ sBuf,
                                          float* __restrict__ dst_f, int lane)
{
    float4* dst = (float4*)dst_f;
    const float4* q = (const float4*)sBuf;
    __stcs(dst + lane,      q[lane]);
    __stcs(dst + lane + 32, q[lane + 32]);
    if (lane < 8) __stcs(dst + lane + 64, q[lane + 64]);
}

__device__ __forceinline__ void stage_buf(float* __restrict__ sBuf,
                                          const float* __restrict__ o, int lane)
{
    #pragma unroll
    for (int k = 0; k < 9; k++) sBuf[lane * 9 + k] = o[k];
}

// One 32-point subtile: compute, then alternate staging buffers b0/b1.
// Every flush of a buffer is separated from that buffer's next stage by a
// syncwarp in program order, so overwrite ordering holds with 3 syncs.
__device__ __forceinline__ void do_subtile(const float* __restrict__ sIn,
                                           float* __restrict__ b0,
                                           float* __restrict__ b1,
                                           float* __restrict__ out,
                                           size_t nn, long base, int lane)
{
    float Fp[9], o1[9], o2[9], o3[9];
    #pragma unroll
    for (int k = 0; k < 9; k++) Fp[k] = sIn[lane * 9 + k];

    compute_point(Fp, o1, o2, o3);

    stage_buf(b0, o1, lane);
    __syncwarp();
    flush_buf(b0, out + (size_t)base * 9, lane);

    stage_buf(b1, o2, lane);
    __syncwarp();
    flush_buf(b1, out + nn + (size_t)base * 9, lane);

    stage_buf(b0, o3, lane);
    __syncwarp();
    flush_buf(b0, out + 2 * nn + (size_t)base * 9, lane);
}

__device__ __forceinline__ void prefetch_subtile(uint32_t dstBase,
                                                 const float4* __restrict__ src,
                                                 int lane)
{
    cp_async16(dstBase + lane * 16,        src + lane);
    cp_async16(dstBase + (lane + 32) * 16, src + lane + 32);
    if (lane < 8) cp_async16(dstBase + (lane + 64) * 16, src + lane + 64);
    cp_commit();
}

__global__ __launch_bounds__(BS, 9)
void hyper_kernel(const float* __restrict__ Fin,
                  float* __restrict__ out,
                  int n)
{
    __shared__ __align__(16) float sIn[WPB][3][288];   // triple-buffered input (13.5 KB)
    __shared__ __align__(16) float sOut[WPB][2][288];  // rotating output buffers (9 KB)

    const int warp = threadIdx.x >> 5;
    const int lane = threadIdx.x & 31;
    const long base0 = (long)blockIdx.x * (BS * 3) + warp * 96;  // 96 pts/warp
    const size_t nn = (size_t)n * 9;

    float* b0 = sOut[warp][0];
    float* b1 = sOut[warp][1];

    if (base0 + 96 <= n) {
        // issue ALL three subtiles' prefetches up-front (6.75 cp.async/lane)
        prefetch_subtile(smem_u32(sIn[warp][0]),
                         (const float4*)(Fin + (size_t)base0 * 9), lane);
        prefetch_subtile(smem_u32(sIn[warp][1]),
                         (const float4*)(Fin + (size_t)(base0 + 32) * 9), lane);
        prefetch_subtile(smem_u32(sIn[warp][2]),
                         (const float4*)(Fin + (size_t)(base0 + 64) * 9), lane);

        cp_wait2();                     // subtile 0 landed
        __syncwarp();
        do_subtile(sIn[warp][0], b0, b1, out, nn, base0, lane);

        cp_wait1();                     // subtile 1 landed
        __syncwarp();
        do_subtile(sIn[warp][1], b0, b1, out, nn, base0 + 32, lane);

        cp_wait0();                     // subtile 2 landed
        __syncwarp();
        do_subtile(sIn[warp][2], b0, b1, out, nn, base0 + 64, lane);
    } else {
        // ---- tail: scalar guarded path ----
        #pragma unroll
        for (int s = 0; s < 3; s++) {
            long idx = base0 + s * 32 + lane;
            if (idx < n) {
                float Fp[9], o1[9], o2[9], o3[9];
                #pragma unroll
                for (int k = 0; k < 9; k++) Fp[k] = Fin[(size_t)idx * 9 + k];
                compute_point(Fp, o1, o2, o3);
                #pragma unroll
                for (int k = 0; k < 9; k++) {
                    out[(size_t)idx * 9 + k]          = o1[k];
                    out[nn + (size_t)idx * 9 + k]     = o2[k];
                    out[2 * nn + (size_t)idx * 9 + k] = o3[k];
                }
            }
        }
    }
}

extern "C" void kernel_launch(void* const* d_in, const int* in_sizes, int n_in,
                              void* d_out, int out_size)
{
    const float* F = (const float*)d_in[0];
    float* out = (float*)d_out;
    int n = in_sizes[0] / 9;

    int pts_per_block = BS * 3;   // 96 per warp, 4 warps
    int blocks = (n + pts_per_block - 1) / pts_per_block;
    hyper_kernel<<<blocks, BS>>>(F, out, n);
}